// round 5
// baseline (speedup 1.0000x reference)
#include <cuda_runtime.h>

// Occupancy connectivity loss over a 385^3 fp32 grid, C order:
//   f = x*385^2 + y*385 + z
// Block = 8 warps = 8 consecutive y-rows of a 128-wide z segment (+1 halo
// column), marching over an x chunk. Per x-plane each warp loads its row ONCE
// (4 coalesced LDG.32 + lane31 halo scalar):
//   x-diff: previous plane's registers
//   z-diff: shfl_down within the warp (no L1 traffic)
//   y-diff: neighbor warp's row via double-buffered shared memory
// Rows loaded 8, owned 7. Steady-state loop is peeled -> branch-free body.

#define ROW    385u
#define PLANE  148225u
#define WPB    8u
#define OWN    7u
#define NYG    55u
#define XC     5u
#define NZSEG  3u
#define NBLOCKS (NZSEG * NYG * XC)   // 825

__device__ double   g_part[NBLOCKS];
__device__ unsigned g_count = 0;

__global__ void __launch_bounds__(256, 6)
occ_main(const float* __restrict__ occ, float* __restrict__ out) {
    const unsigned wid  = threadIdx.x >> 5;
    const unsigned lane = threadIdx.x & 31u;
    const bool     l31  = (lane == 31u);

    const unsigned zseg = blockIdx.x % NZSEG;
    const unsigned rest = blockIdx.x / NZSEG;
    const unsigned xc   = rest % XC;
    const unsigned g    = rest / XC;

    const unsigned zb = zseg * 128u;
    const unsigned yb = g * OWN;
    const unsigned y  = yb + wid;
    const bool rowload = (y <= 384u);
    const bool rowown  = (wid < OWN) && rowload;
    const bool ypair   = rowown && (y < 384u);
    const bool haloseg = (zseg == 2u);          // owns z=384 column diffs

    const unsigned as = (384u * xc) / XC;
    const unsigned ae = (384u * (xc + 1u)) / XC;
    const bool lastc  = (ae == 384u);
    const int  mid    = (int)(ae - as) - 1;     // planes strictly between

    __shared__ float sm[2][WPB][132];

    const float* pc = occ + (size_t)y * ROW + zb + lane + (size_t)as * PLANE;

    float s = 0.0f;
    float v0=0.f,v1=0.f,v2=0.f,v3=0.f,hc=0.f;     // current plane
    float n0=0.f,n1=0.f,n2=0.f,n3=0.f,hn=0.f;     // prefetched plane
    float q0=0.f,q1=0.f,q2=0.f,q3=0.f,hq=0.f;     // previous plane

    #define LDROW(P,a0,a1,a2,a3,ah) do {                       \
        a0=__ldg(P); a1=__ldg((P)+32);                         \
        a2=__ldg((P)+64); a3=__ldg((P)+96);                    \
        if (l31) ah=__ldg((P)+97); } while(0)

    #define PUB(B) do { float* r_ = sm[B][wid];                \
        r_[lane]=v0; r_[lane+32u]=v1;                          \
        r_[lane+64u]=v2; r_[lane+96u]=v3;                      \
        if (l31) r_[128]=hc; } while(0)

    // z-diffs (shuffle) + y-diffs (smem) for the current plane
    #define ZY(B) do {                                                      \
        float z0=__shfl_down_sync(0xffffffffu,v0,1);                        \
        float z1=__shfl_down_sync(0xffffffffu,v1,1);                        \
        float z2=__shfl_down_sync(0xffffffffu,v2,1);                        \
        float z3=__shfl_down_sync(0xffffffffu,v3,1);                        \
        float b1=__shfl_sync(0xffffffffu,v1,0);                             \
        float b2=__shfl_sync(0xffffffffu,v2,0);                             \
        float b3=__shfl_sync(0xffffffffu,v3,0);                             \
        if (l31) { z0=b1; z1=b2; z2=b3; z3=hc; }                            \
        s += fabsf(z0-v0)+fabsf(z1-v1)+fabsf(z2-v2)+fabsf(z3-v3);           \
        if (ypair) {                                                        \
            const float* q_ = sm[B][wid+1u];                                \
            s += fabsf(q_[lane]-v0)+fabsf(q_[lane+32u]-v1)                  \
               + fabsf(q_[lane+64u]-v2)+fabsf(q_[lane+96u]-v3);             \
            if (haloseg && l31) s += fabsf(q_[128]-hc);                     \
        } } while(0)

    #define XD() do {                                                       \
        s += fabsf(v0-q0)+fabsf(v1-q1)+fabsf(v2-q2)+fabsf(v3-q3);           \
        if (haloseg && l31) s += fabsf(hc-hq); } while(0)

    #define ROTATE() do { q0=v0;q1=v1;q2=v2;q3=v3;hq=hc;                    \
                          v0=n0;v1=n1;v2=n2;v3=n3;hc=hn; } while(0)

    // ---- first plane (x = as): z/y diffs only ----
    if (rowload) LDROW(pc, v0,v1,v2,v3,hc);
    const float* pn = pc + PLANE;
    if (rowload) { PUB(0); LDROW(pn, n0,n1,n2,n3,hn); }
    __syncthreads();
    if (rowown) ZY(0);
    ROTATE();

    // ---- steady planes (x = as+1 .. ae-1): branch-free body ----
    unsigned buf = 1u;
    #pragma unroll 2
    for (int i = 0; i < mid; ++i) {
        pn += PLANE;
        if (rowload) { PUB(buf); LDROW(pn, n0,n1,n2,n3,hn); }
        __syncthreads();
        if (rowown) { XD(); ZY(buf); }
        ROTATE();
        buf ^= 1u;
    }

    // ---- last plane (x = ae): x-diffs always, z/y only for the last chunk ----
    if (rowload) PUB(buf);
    __syncthreads();
    if (rowown) { XD(); if (lastc) ZY(buf); }

    // ---- block reduction ----
    #pragma unroll
    for (int o = 16; o > 0; o >>= 1)
        s += __shfl_down_sync(0xffffffffu, s, o);

    __shared__ float    ws[WPB];
    __shared__ unsigned islast_s;
    if (lane == 0u) ws[wid] = s;
    __syncthreads();
    if (threadIdx.x == 0u) {
        float t = 0.f;
        #pragma unroll
        for (unsigned i = 0; i < WPB; ++i) t += ws[i];
        g_part[blockIdx.x] = (double)t;
        __threadfence();
        unsigned old = atomicAdd(&g_count, 1u);
        islast_s = (old == NBLOCKS - 1u) ? 1u : 0u;
    }
    __syncthreads();

    // ---- last block folds partials (single launch total) ----
    if (islast_s) {
        double d = 0.0;
        for (unsigned i = threadIdx.x; i < NBLOCKS; i += 256u)
            d += g_part[i];
        __shared__ double dsm[256];
        dsm[threadIdx.x] = d;
        __syncthreads();
        #pragma unroll
        for (int st = 128; st > 0; st >>= 1) {
            if ((int)threadIdx.x < st) dsm[threadIdx.x] += dsm[threadIdx.x + st];
            __syncthreads();
        }
        if (threadIdx.x == 0u) {
            out[0] = (float)dsm[0];
            g_count = 0u;   // reset for next graph replay
        }
    }
}

extern "C" void kernel_launch(void* const* d_in, const int* in_sizes, int n_in,
                              void* d_out, int out_size) {
    const float* occ = (const float*)d_in[0];
    float* out = (float*)d_out;
    occ_main<<<NBLOCKS, 256>>>(occ, out);
}

// round 6
// speedup vs baseline: 1.1095x; 1.1095x over previous
#include <cuda_runtime.h>

// Occupancy connectivity loss over a 385^3 fp32 grid, C order:
//   f = x*385^2 + y*385 + z
// Block = 8 warps = 8 consecutive y-rows of a 96-wide z segment (+1 halo
// column), marching over an x chunk. Per x-plane each warp loads its row ONCE
// (3 coalesced LDG.32 + lane31 halo scalar):
//   x-diff: previous plane's registers
//   z-diff: own smem row at +1 (halo column handled naturally)
//   y-diff: neighbor warp's row via double-buffered shared memory
// 96-z (not 128) cuts live registers so 8 blocks/SM fit (64 warps: latency).

#define ROW    385u
#define PLANE  148225u
#define WPB    8u
#define OWN    7u
#define NYG    55u
#define XC     5u
#define NZSEG  4u                     // z segs: 0,96,192,288 (+halo 384)
#define NBLOCKS (NZSEG * NYG * XC)    // 1100

__device__ double   g_part[NBLOCKS];
__device__ unsigned g_count = 0;

__global__ void __launch_bounds__(256, 8)
occ_main(const float* __restrict__ occ, float* __restrict__ out) {
    const unsigned wid  = threadIdx.x >> 5;
    const unsigned lane = threadIdx.x & 31u;
    const bool     l31  = (lane == 31u);

    const unsigned zseg = blockIdx.x % NZSEG;
    const unsigned rest = blockIdx.x / NZSEG;
    const unsigned xc   = rest % XC;
    const unsigned g    = rest / XC;

    const unsigned zb = zseg * 96u;
    const unsigned yb = g * OWN;
    const unsigned y  = yb + wid;
    const bool rowload = (y <= 384u);
    const bool rowown  = (wid < OWN) && rowload;
    const bool ypair   = rowown && (y < 384u);
    const bool hseg31  = (zseg == NZSEG - 1u) && l31;  // z=384 col x/y diffs

    const unsigned as = (384u * xc) / XC;
    const unsigned ae = (384u * (xc + 1u)) / XC;
    const bool lastc  = (ae == 384u);
    const int  mid    = (int)(ae - as) - 1;

    __shared__ float sm[2][WPB][100];   // 96 + halo + pad

    // lane-contiguous scalar base; lane31's halo (z=zb+96) sits at rowp+65
    const float* rowp = occ + (size_t)y * ROW + zb + lane + (size_t)as * PLANE;

    float s = 0.0f;
    float v0=0.f,v1=0.f,v2=0.f,hc=0.f;     // current plane
    float n0=0.f,n1=0.f,n2=0.f,hn=0.f;     // prefetched plane
    float q0=0.f,q1=0.f,q2=0.f,hq=0.f;     // previous plane

    #define LDROW(P,a0,a1,a2,ah) do {                          \
        a0=__ldg(P); a1=__ldg((P)+32); a2=__ldg((P)+64);       \
        if (l31) ah=__ldg((P)+65); } while(0)

    #define PUB(B) do { float* r_ = sm[B][wid];                \
        r_[lane]=v0; r_[lane+32u]=v1; r_[lane+64u]=v2;         \
        if (l31) r_[96]=hc; } while(0)

    #define ZY(B) do {                                                      \
        const float* r_ = sm[B][wid];                                       \
        s += fabsf(r_[lane+1u]-v0)+fabsf(r_[lane+33u]-v1)                   \
           + fabsf(r_[lane+65u]-v2);                                        \
        if (ypair) {                                                        \
            const float* q_ = sm[B][wid+1u];                                \
            s += fabsf(q_[lane]-v0)+fabsf(q_[lane+32u]-v1)                  \
               + fabsf(q_[lane+64u]-v2);                                    \
            if (hseg31) s += fabsf(q_[96]-hc);                              \
        } } while(0)

    #define XD() do {                                                       \
        s += fabsf(v0-q0)+fabsf(v1-q1)+fabsf(v2-q2);                        \
        if (hseg31) s += fabsf(hc-hq); } while(0)

    #define ROTATE() do { q0=v0;q1=v1;q2=v2;hq=hc;                          \
                          v0=n0;v1=n1;v2=n2;hc=hn; } while(0)

    // ---- first plane (x = as): z/y diffs only ----
    if (rowload) LDROW(rowp, v0,v1,v2,hc);
    const float* pn = rowp + PLANE;
    if (rowload) { PUB(0); LDROW(pn, n0,n1,n2,hn); }
    __syncthreads();
    if (rowown) ZY(0);
    ROTATE();

    // ---- steady planes: branch-free body ----
    unsigned buf = 1u;
    for (int i = 0; i < mid; ++i) {
        pn += PLANE;
        if (rowload) { PUB(buf); LDROW(pn, n0,n1,n2,hn); }
        __syncthreads();
        if (rowown) { XD(); ZY(buf); }
        ROTATE();
        buf ^= 1u;
    }

    // ---- last plane (x = ae): x-diffs always, z/y only in last chunk ----
    if (rowload) PUB(buf);
    __syncthreads();
    if (rowown) { XD(); if (lastc) ZY(buf); }

    // ---- block reduction ----
    #pragma unroll
    for (int o = 16; o > 0; o >>= 1)
        s += __shfl_down_sync(0xffffffffu, s, o);

    __shared__ float    ws[WPB];
    __shared__ unsigned islast_s;
    if (lane == 0u) ws[wid] = s;
    __syncthreads();
    if (threadIdx.x == 0u) {
        float t = 0.f;
        #pragma unroll
        for (unsigned i = 0; i < WPB; ++i) t += ws[i];
        g_part[blockIdx.x] = (double)t;
        __threadfence();
        unsigned old = atomicAdd(&g_count, 1u);
        islast_s = (old == NBLOCKS - 1u) ? 1u : 0u;
    }
    __syncthreads();

    // ---- last block folds partials (single launch total) ----
    if (islast_s) {
        double d = 0.0;
        for (unsigned i = threadIdx.x; i < NBLOCKS; i += 256u)
            d += g_part[i];
        __shared__ double dsm[256];
        dsm[threadIdx.x] = d;
        __syncthreads();
        #pragma unroll
        for (int st = 128; st > 0; st >>= 1) {
            if ((int)threadIdx.x < st) dsm[threadIdx.x] += dsm[threadIdx.x + st];
            __syncthreads();
        }
        if (threadIdx.x == 0u) {
            out[0] = (float)dsm[0];
            g_count = 0u;   // reset for next graph replay
        }
    }
}

extern "C" void kernel_launch(void* const* d_in, const int* in_sizes, int n_in,
                              void* d_out, int out_size) {
    const float* occ = (const float*)d_in[0];
    float* out = (float*)d_out;
    occ_main<<<NBLOCKS, 256>>>(occ, out);
}